// round 2
// baseline (speedup 1.0000x reference)
#include <cuda_runtime.h>
#include <cuda_bf16.h>
#include <math.h>

// ---------------- problem constants ----------------
#define TT    2048
#define DD    4096
#define HH    16
#define DHD   256
#define DFF   16384
#define ROTD  64

// ---------------- scratch (device globals; no cudaMalloc allowed) ----------------
__device__ float g_h  [TT * DD];
__device__ float g_q  [TT * DD];
__device__ float g_k  [TT * DD];
__device__ float g_v  [TT * DD];
__device__ float g_y  [TT * DD];
__device__ float g_tmp[TT * DD];
__device__ float g_m  [TT * DFF];

// ---------------- LayerNorm ----------------
__global__ __launch_bounds__(256) void ln_kernel(const float* __restrict__ x,
                                                 const float* __restrict__ g,
                                                 const float* __restrict__ b,
                                                 float* __restrict__ h) {
    int row = blockIdx.x;
    const float4* xr = (const float4*)(x + (size_t)row * DD);
    float s = 0.f, s2 = 0.f;
    for (int i = threadIdx.x; i < DD / 4; i += 256) {
        float4 v = xr[i];
        s  += v.x + v.y + v.z + v.w;
        s2 += v.x*v.x + v.y*v.y + v.z*v.z + v.w*v.w;
    }
    for (int o = 16; o > 0; o >>= 1) {
        s  += __shfl_xor_sync(~0u, s,  o);
        s2 += __shfl_xor_sync(~0u, s2, o);
    }
    __shared__ float sh[16];
    int w = threadIdx.x >> 5;
    if ((threadIdx.x & 31) == 0) { sh[w] = s; sh[8 + w] = s2; }
    __syncthreads();
    if (threadIdx.x < 32) {
        float a = threadIdx.x < 8 ? sh[threadIdx.x]     : 0.f;
        float c = threadIdx.x < 8 ? sh[8 + threadIdx.x] : 0.f;
        for (int o = 4; o > 0; o >>= 1) {
            a += __shfl_xor_sync(~0u, a, o);
            c += __shfl_xor_sync(~0u, c, o);
        }
        if (threadIdx.x == 0) { sh[0] = a; sh[8] = c; }
    }
    __syncthreads();
    float mean = sh[0] * (1.f / DD);
    float var  = sh[8] * (1.f / DD) - mean * mean;
    float rstd = rsqrtf(var + 1e-6f);
    float4* hr = (float4*)(h + (size_t)row * DD);
    const float4* gg4 = (const float4*)g;
    const float4* bb4 = (const float4*)b;
    for (int i = threadIdx.x; i < DD / 4; i += 256) {
        float4 v = xr[i], gg = gg4[i], bb = bb4[i], o;
        o.x = (v.x - mean) * rstd * gg.x + bb.x;
        o.y = (v.y - mean) * rstd * gg.y + bb.y;
        o.z = (v.z - mean) * rstd * gg.z + bb.z;
        o.w = (v.w - mean) * rstd * gg.w + bb.w;
        hr[i] = o;
    }
}

// ---------------- RoPE (applied in-place to q and k) ----------------
__global__ __launch_bounds__(256) void rope_kernel(float* __restrict__ q, float* __restrict__ k) {
    int idx = blockIdx.x * 256 + threadIdx.x;   // T*H*32 threads
    int f = idx & 31;
    int hh = (idx >> 5) & (HH - 1);
    int t = idx >> 9;
    float inv = 1.0f / powf(10000.0f, (float)f * (1.0f / 32.0f));
    float ang = (float)t * inv;                 // fp32 to mimic reference rounding
    float sn, cs;
    sincosf(ang, &sn, &cs);
    size_t base = (size_t)t * DD + hh * DHD + f;
    {
        float a = q[base], b = q[base + 32];
        q[base]      = a * cs - b * sn;
        q[base + 32] = a * sn + b * cs;
    }
    {
        float a = k[base], b = k[base + 32];
        k[base]      = a * cs - b * sn;
        k[base + 32] = a * sn + b * cs;
    }
}

// ---------------- GEMM 128x128x16, 256 threads, 8x8 microtiles ----------------
// EPI: 0 = store, 1 = gelu(acc+bias), 2 = acc+res, 3 = acc+bias+res
__device__ __forceinline__ float gelu_f(float v) {
    float t = tanhf(0.7978845608028654f * (v + 0.044715f * v * v * v));
    return 0.5f * v * (1.f + t);
}

template <int EPI>
__device__ __forceinline__ void sgemm_body(const float* __restrict__ A, const float* __restrict__ B,
                                           const float* __restrict__ bias, const float* __restrict__ res,
                                           float* __restrict__ C, int N, int K) {
    __shared__ float As[16][132];
    __shared__ float Bs[16][128];
    int tid = threadIdx.x;
    int bm = blockIdx.y * 128, bn = blockIdx.x * 128;
    int tr = tid >> 4, tc = tid & 15;

    int arow = tid >> 2, ak = (tid & 3) << 2;
    int brow = tid >> 5, bc = (tid & 31) << 2;
    const float* Aptr = A + (size_t)(bm + arow) * K + ak;
    const float* Bptr = B + (size_t)brow * N + bn + bc;

    float4 aReg0 = *(const float4*)Aptr;
    float4 aReg1 = *(const float4*)(Aptr + (size_t)64 * K);
    float4 bReg0 = *(const float4*)Bptr;
    float4 bReg1 = *(const float4*)(Bptr + (size_t)8 * N);

    float acc[8][8];
#pragma unroll
    for (int i = 0; i < 8; ++i)
#pragma unroll
        for (int j = 0; j < 8; ++j) acc[i][j] = 0.f;

    int ntiles = K >> 4;
    for (int kt = 0; kt < ntiles; ++kt) {
        As[ak + 0][arow]      = aReg0.x;
        As[ak + 1][arow]      = aReg0.y;
        As[ak + 2][arow]      = aReg0.z;
        As[ak + 3][arow]      = aReg0.w;
        As[ak + 0][64 + arow] = aReg1.x;
        As[ak + 1][64 + arow] = aReg1.y;
        As[ak + 2][64 + arow] = aReg1.z;
        As[ak + 3][64 + arow] = aReg1.w;
        *(float4*)&Bs[brow][bc]     = bReg0;
        *(float4*)&Bs[brow + 8][bc] = bReg1;
        __syncthreads();

        if (kt + 1 < ntiles) {
            Aptr += 16;
            Bptr += (size_t)16 * N;
            aReg0 = *(const float4*)Aptr;
            aReg1 = *(const float4*)(Aptr + (size_t)64 * K);
            bReg0 = *(const float4*)Bptr;
            bReg1 = *(const float4*)(Bptr + (size_t)8 * N);
        }

#pragma unroll
        for (int kk = 0; kk < 16; ++kk) {
            float a[8], b[8];
            *(float4*)&a[0] = *(const float4*)&As[kk][tr * 4];
            *(float4*)&a[4] = *(const float4*)&As[kk][64 + tr * 4];
            *(float4*)&b[0] = *(const float4*)&Bs[kk][tc * 4];
            *(float4*)&b[4] = *(const float4*)&Bs[kk][64 + tc * 4];
#pragma unroll
            for (int i = 0; i < 8; ++i)
#pragma unroll
                for (int j = 0; j < 8; ++j) acc[i][j] += a[i] * b[j];
        }
        __syncthreads();
    }

    // epilogue
#pragma unroll
    for (int ih = 0; ih < 2; ++ih) {
#pragma unroll
        for (int i = 0; i < 4; ++i) {
            int r = bm + ih * 64 + tr * 4 + i;
#pragma unroll
            for (int jh = 0; jh < 2; ++jh) {
                int c = bn + jh * 64 + tc * 4;
                float4 v;
                v.x = acc[ih * 4 + i][jh * 4 + 0];
                v.y = acc[ih * 4 + i][jh * 4 + 1];
                v.z = acc[ih * 4 + i][jh * 4 + 2];
                v.w = acc[ih * 4 + i][jh * 4 + 3];
                if (EPI == 1) {
                    float4 bb = *(const float4*)(bias + c);
                    v.x = gelu_f(v.x + bb.x);
                    v.y = gelu_f(v.y + bb.y);
                    v.z = gelu_f(v.z + bb.z);
                    v.w = gelu_f(v.w + bb.w);
                } else if (EPI == 2) {
                    float4 rr = *(const float4*)(res + (size_t)r * N + c);
                    v.x += rr.x; v.y += rr.y; v.z += rr.z; v.w += rr.w;
                } else if (EPI == 3) {
                    float4 bb = *(const float4*)(bias + c);
                    float4 rr = *(const float4*)(res + (size_t)r * N + c);
                    v.x += bb.x + rr.x; v.y += bb.y + rr.y;
                    v.z += bb.z + rr.z; v.w += bb.w + rr.w;
                }
                *(float4*)&C[(size_t)r * N + c] = v;
            }
        }
    }
}

template <int EPI>
__global__ __launch_bounds__(256) void gemm_kernel(const float* __restrict__ A, const float* __restrict__ B,
                                                   const float* __restrict__ bias, const float* __restrict__ res,
                                                   float* __restrict__ C, int N, int K) {
    sgemm_body<EPI>(A, B, bias, res, C, N, K);
}

__global__ __launch_bounds__(256) void qkv_kernel(const float* __restrict__ h,
                                                  const float* __restrict__ wq, const float* __restrict__ wk,
                                                  const float* __restrict__ wv,
                                                  float* __restrict__ q, float* __restrict__ k, float* __restrict__ v) {
    const float* B = (blockIdx.z == 0) ? wq : (blockIdx.z == 1) ? wk : wv;
    float* C       = (blockIdx.z == 0) ? q  : (blockIdx.z == 1) ? k  : v;
    sgemm_body<0>(h, B, nullptr, nullptr, C, DD, DD);
}

// ---------------- Flash attention (fp32, Br=Bc=64, online softmax) ----------------
#define QS_STRIDE 260
#define PS_STRIDE 68
#define ATTN_SMEM ((3 * 64 * QS_STRIDE + 64 * PS_STRIDE) * 4)

__global__ __launch_bounds__(256) void attn_kernel(const float* __restrict__ q,
                                                   const float* __restrict__ k,
                                                   const float* __restrict__ v,
                                                   float* __restrict__ y) {
    extern __shared__ float sm[];
    float* Qs = sm;
    float* Ks = Qs + 64 * QS_STRIDE;
    float* Vs = Ks + 64 * QS_STRIDE;
    float* Ps = Vs + 64 * QS_STRIDE;

    int qt = blockIdx.x, hh = blockIdx.y;
    int tid = threadIdx.x, ty = tid >> 4, tx = tid & 15;
    int r0 = ty * 4, c0 = tx * 4;
    size_t hoff = (size_t)hh * DHD;

    // load Q tile (pre-scaled by 1/sqrt(Dh) = 1/16)
    for (int i = tid; i < 64 * 64; i += 256) {
        int row = i >> 6, c4 = i & 63;
        float4 t = *(const float4*)(q + (size_t)(qt * 64 + row) * DD + hoff + c4 * 4);
        t.x *= 0.0625f; t.y *= 0.0625f; t.z *= 0.0625f; t.w *= 0.0625f;
        *(float4*)&Qs[row * QS_STRIDE + c4 * 4] = t;
    }

    float O[4][16];
#pragma unroll
    for (int i = 0; i < 4; ++i)
#pragma unroll
        for (int cc = 0; cc < 16; ++cc) O[i][cc] = 0.f;
    float mrow[4] = {-1e30f, -1e30f, -1e30f, -1e30f};
    float lrow[4] = {0.f, 0.f, 0.f, 0.f};

    for (int kt = 0; kt <= qt; ++kt) {
        __syncthreads();  // protect Ks/Vs/Ps (and Qs on first iteration)
        for (int i = tid; i < 64 * 64; i += 256) {
            int row = i >> 6, c4 = i & 63;
            *(float4*)&Ks[row * QS_STRIDE + c4 * 4] =
                *(const float4*)(k + (size_t)(kt * 64 + row) * DD + hoff + c4 * 4);
            *(float4*)&Vs[row * QS_STRIDE + c4 * 4] =
                *(const float4*)(v + (size_t)(kt * 64 + row) * DD + hoff + c4 * 4);
        }
        __syncthreads();

        float S[4][4];
#pragma unroll
        for (int i = 0; i < 4; ++i)
#pragma unroll
            for (int j = 0; j < 4; ++j) S[i][j] = 0.f;

#pragma unroll 8
        for (int d4 = 0; d4 < 64; ++d4) {
            float4 qa[4], kb[4];
#pragma unroll
            for (int i = 0; i < 4; ++i) qa[i] = *(const float4*)&Qs[(r0 + i) * QS_STRIDE + d4 * 4];
#pragma unroll
            for (int j = 0; j < 4; ++j) kb[j] = *(const float4*)&Ks[(c0 + j) * QS_STRIDE + d4 * 4];
#pragma unroll
            for (int i = 0; i < 4; ++i)
#pragma unroll
                for (int j = 0; j < 4; ++j)
                    S[i][j] += qa[i].x * kb[j].x + qa[i].y * kb[j].y + qa[i].z * kb[j].z + qa[i].w * kb[j].w;
        }

        if (kt == qt) {
#pragma unroll
            for (int i = 0; i < 4; ++i)
#pragma unroll
                for (int j = 0; j < 4; ++j)
                    if (c0 + j > r0 + i) S[i][j] = -1e30f;
        }

#pragma unroll
        for (int i = 0; i < 4; ++i) {
            float tm = fmaxf(fmaxf(S[i][0], S[i][1]), fmaxf(S[i][2], S[i][3]));
            for (int o = 8; o > 0; o >>= 1) tm = fmaxf(tm, __shfl_xor_sync(~0u, tm, o, 16));
            float nm = fmaxf(mrow[i], tm);
            float alpha = expf(mrow[i] - nm);
            mrow[i] = nm;
            float rs = 0.f;
#pragma unroll
            for (int j = 0; j < 4; ++j) {
                float p = expf(S[i][j] - nm);
                S[i][j] = p;
                rs += p;
            }
            for (int o = 8; o > 0; o >>= 1) rs += __shfl_xor_sync(~0u, rs, o, 16);
            lrow[i] = lrow[i] * alpha + rs;
#pragma unroll
            for (int cc = 0; cc < 16; ++cc) O[i][cc] *= alpha;
            float4 pp;
            pp.x = S[i][0]; pp.y = S[i][1]; pp.z = S[i][2]; pp.w = S[i][3];
            *(float4*)&Ps[(r0 + i) * PS_STRIDE + c0] = pp;
        }
        __syncthreads();

        // O += P @ V
#pragma unroll 4
        for (int j = 0; j < 64; ++j) {
            float pv[4];
#pragma unroll
            for (int i = 0; i < 4; ++i) pv[i] = Ps[(r0 + i) * PS_STRIDE + j];
#pragma unroll
            for (int cc = 0; cc < 16; ++cc) {
                float vv = Vs[j * QS_STRIDE + cc * 16 + tx];
#pragma unroll
                for (int i = 0; i < 4; ++i) O[i][cc] += pv[i] * vv;
            }
        }
    }

#pragma unroll
    for (int i = 0; i < 4; ++i) {
        float inv = 1.f / lrow[i];
        size_t rb = (size_t)(qt * 64 + r0 + i) * DD + hoff;
#pragma unroll
        for (int cc = 0; cc < 16; ++cc) y[rb + cc * 16 + tx] = O[i][cc] * inv;
    }
}

// ---------------- launcher ----------------
extern "C" void kernel_launch(void* const* d_in, const int* in_sizes, int n_in,
                              void* d_out, int out_size) {
    const float* x       = (const float*)d_in[0];
    const float* wq      = (const float*)d_in[1];
    const float* wk      = (const float*)d_in[2];
    const float* wv      = (const float*)d_in[3];
    const float* wo      = (const float*)d_in[4];
    const float* w_in    = (const float*)d_in[5];
    const float* b_in    = (const float*)d_in[6];
    const float* w_out   = (const float*)d_in[7];
    const float* b_out   = (const float*)d_in[8];
    const float* ln_s    = (const float*)d_in[9];
    const float* ln_o    = (const float*)d_in[10];
    float* out = (float*)d_out;

    float *h, *q, *k, *v, *y, *tmp, *m;
    cudaGetSymbolAddress((void**)&h,   g_h);
    cudaGetSymbolAddress((void**)&q,   g_q);
    cudaGetSymbolAddress((void**)&k,   g_k);
    cudaGetSymbolAddress((void**)&v,   g_v);
    cudaGetSymbolAddress((void**)&y,   g_y);
    cudaGetSymbolAddress((void**)&tmp, g_tmp);
    cudaGetSymbolAddress((void**)&m,   g_m);

    cudaFuncSetAttribute(attn_kernel, cudaFuncAttributeMaxDynamicSharedMemorySize, ATTN_SMEM);

    // 1. LayerNorm
    ln_kernel<<<TT, 256>>>(x, ln_s, ln_o, h);
    // 2. QKV projections (z-batched)
    qkv_kernel<<<dim3(DD / 128, TT / 128, 3), 256>>>(h, wq, wk, wv, q, k, v);
    // 3. RoPE on q, k
    rope_kernel<<<(TT * HH * 32) / 256, 256>>>(q, k);
    // 4. Causal flash attention
    attn_kernel<<<dim3(TT / 64, HH), 256, ATTN_SMEM>>>(q, k, v, y);
    // 5. tmp = y @ wo + x
    gemm_kernel<2><<<dim3(DD / 128, TT / 128), 256>>>(y, wo, nullptr, x, tmp, DD, DD);
    // 6. m = gelu(h @ w_in + b_in)
    gemm_kernel<1><<<dim3(DFF / 128, TT / 128), 256>>>(h, w_in, b_in, nullptr, m, DFF, DD);
    // 7. out = m @ w_out + b_out + tmp
    gemm_kernel<3><<<dim3(DD / 128, TT / 128), 256>>>(m, w_out, b_out, tmp, out, DD, DFF);
}